// round 2
// baseline (speedup 1.0000x reference)
#include <cuda_runtime.h>
#include <cuda_bf16.h>

// Problem constants (fixed shapes per reference)
#define B_SZ   4
#define S_SZ   4096
#define T_TOK  (B_SZ * S_SZ)       // 16384 tokens
#define H_DIM  1024
#define I_DIM  3584
#define E_NUM  8
#define TOPK   2

// ---------------- static device scratch (no allocations allowed) ----------------
__device__ int   g_count[E_NUM];
__device__ int   g_off[E_NUM + 1];
__device__ int   g_tok[E_NUM * T_TOK];      // per-expert token lists (capacity T each)
__device__ float g_wt[E_NUM * T_TOK];       // per-entry combine weight
__device__ float g_hidden[(size_t)TOPK * T_TOK * I_DIM];  // 32768 x 3584 fp32 (~470 MB)

// ---------------- kernels ----------------

__global__ void zero_out_kernel(float* __restrict__ out, int n4) {
    int i = blockIdx.x * blockDim.x + threadIdx.x;
    if (i < n4) ((float4*)out)[i] = make_float4(0.f, 0.f, 0.f, 0.f);
}

__global__ void zero_counts_kernel() {
    if (threadIdx.x < E_NUM) g_count[threadIdx.x] = 0;
}

// One warp per token: logits over 8 experts, top-2, renormalized weights, gather.
__global__ void router_kernel(const float* __restrict__ x, const float* __restrict__ gw) {
    int warp = (blockIdx.x * blockDim.x + threadIdx.x) >> 5;
    int lane = threadIdx.x & 31;
    if (warp >= T_TOK) return;
    const float* xr = x + (size_t)warp * H_DIM;

    float xs[H_DIM / 32];
#pragma unroll
    for (int i = 0; i < H_DIM / 32; i++) xs[i] = xr[lane + 32 * i];

    float logits[E_NUM];
#pragma unroll
    for (int e = 0; e < E_NUM; e++) {
        const float* g = gw + e * H_DIM;
        float s = 0.f;
#pragma unroll
        for (int i = 0; i < H_DIM / 32; i++) s += xs[i] * g[lane + 32 * i];
#pragma unroll
        for (int o = 16; o > 0; o >>= 1) s += __shfl_xor_sync(0xffffffffu, s, o);
        logits[e] = s;
    }

    if (lane == 0) {
        // top-1 (strict > keeps lowest index on ties, matching lax.top_k)
        int i1 = 0; float l1 = logits[0];
#pragma unroll
        for (int e = 1; e < E_NUM; e++) if (logits[e] > l1) { l1 = logits[e]; i1 = e; }
        // top-2
        int i2 = -1; float l2 = -3.4e38f;
#pragma unroll
        for (int e = 0; e < E_NUM; e++) {
            if (e == i1) continue;
            if (logits[e] > l2) { l2 = logits[e]; i2 = e; }
        }
        // softmax is monotonic: renormalized top-2 weights need only the two logits
        float e1 = __expf(l1 - l1);           // = 1
        float e2 = __expf(l2 - l1);
        float inv = 1.f / (e1 + e2);
        float w1 = e1 * inv, w2 = e2 * inv;

        int p1 = atomicAdd(&g_count[i1], 1);
        g_tok[i1 * T_TOK + p1] = warp;
        g_wt [i1 * T_TOK + p1] = w1;
        int p2 = atomicAdd(&g_count[i2], 1);
        g_tok[i2 * T_TOK + p2] = warp;
        g_wt [i2 * T_TOK + p2] = w2;
    }
}

__global__ void offsets_kernel() {
    if (threadIdx.x == 0) {
        int o = 0;
        for (int e = 0; e < E_NUM; e++) { g_off[e] = o; o += g_count[e]; }
        g_off[E_NUM] = o;
    }
}

// ---- Pass A: hidden = silu(Xg @ w1[e]) * (Xg @ w3[e]) per expert (gathered rows) ----
// Tiles: BM=64, BN=64, BK=16; 256 threads; 4x4 micro-tile; two accumulators.
__global__ __launch_bounds__(256)
void moe_pass_a(const float* __restrict__ x,
                const float* __restrict__ w1,
                const float* __restrict__ w3) {
    const int e     = blockIdx.z;
    const int mtile = blockIdx.y;
    const int n0    = blockIdx.x * 64;

    const int cnt = g_count[e];
    if (mtile * 64 >= cnt) return;
    const int off = g_off[e];

    __shared__ float As[16][65];
    __shared__ float B1s[16][64];
    __shared__ float B3s[16][64];

    const int t   = threadIdx.x;
    const int lr  = t >> 2;            // 0..63 : x-row to load
    const int lk4 = (t & 3) * 4;       // k offset for x load
    const int wr  = t >> 4;            // 0..15 : weight row (kk) to load
    const int wc  = (t & 15) * 4;      // weight col
    const int ty4 = (t >> 4) * 4;      // 0..60 : compute row base
    const int tx4 = (t & 15) * 4;      // compute col base

    const int mload = mtile * 64 + lr;
    const int tokl  = g_tok[e * T_TOK + min(mload, cnt - 1)];
    const float* xrow = x + (size_t)tokl * H_DIM;

    float acc1[4][4] = {}, acc3[4][4] = {};

    for (int k0 = 0; k0 < H_DIM; k0 += 16) {
        float4 xa = *(const float4*)(xrow + k0 + lk4);
        const size_t wbase = ((size_t)e * H_DIM + k0 + wr) * I_DIM + n0 + wc;
        float4 b1 = *(const float4*)(w1 + wbase);
        float4 b3 = *(const float4*)(w3 + wbase);
        __syncthreads();
        As[lk4 + 0][lr] = xa.x;
        As[lk4 + 1][lr] = xa.y;
        As[lk4 + 2][lr] = xa.z;
        As[lk4 + 3][lr] = xa.w;
        *(float4*)&B1s[wr][wc] = b1;
        *(float4*)&B3s[wr][wc] = b3;
        __syncthreads();
#pragma unroll
        for (int kk = 0; kk < 16; kk++) {
            float a[4];
#pragma unroll
            for (int r = 0; r < 4; r++) a[r] = As[kk][ty4 + r];
            float4 v1 = *(const float4*)&B1s[kk][tx4];
            float4 v3 = *(const float4*)&B3s[kk][tx4];
            float bv1[4] = {v1.x, v1.y, v1.z, v1.w};
            float bv3[4] = {v3.x, v3.y, v3.z, v3.w};
#pragma unroll
            for (int r = 0; r < 4; r++)
#pragma unroll
                for (int c = 0; c < 4; c++) {
                    acc1[r][c] += a[r] * bv1[c];
                    acc3[r][c] += a[r] * bv3[c];
                }
        }
    }

    // epilogue: SwiGLU, store to hidden scratch
#pragma unroll
    for (int r = 0; r < 4; r++) {
        int m = mtile * 64 + ty4 + r;
        if (m < cnt) {
            float4 hv;
            float z;
            z = acc1[r][0]; hv.x = (z / (1.f + __expf(-z))) * acc3[r][0];
            z = acc1[r][1]; hv.y = (z / (1.f + __expf(-z))) * acc3[r][1];
            z = acc1[r][2]; hv.z = (z / (1.f + __expf(-z))) * acc3[r][2];
            z = acc1[r][3]; hv.w = (z / (1.f + __expf(-z))) * acc3[r][3];
            *(float4*)&g_hidden[(size_t)(off + m) * I_DIM + n0 + tx4] = hv;
        }
    }
}

// ---- Pass B: y = hidden @ w2[e]; out[token] += weight * y (atomic scatter-add) ----
__global__ __launch_bounds__(256)
void moe_pass_b(const float* __restrict__ w2, float* __restrict__ out) {
    const int e     = blockIdx.z;
    const int mtile = blockIdx.y;
    const int n0    = blockIdx.x * 64;

    const int cnt = g_count[e];
    if (mtile * 64 >= cnt) return;
    const int off = g_off[e];

    __shared__ float As[16][65];
    __shared__ float Bs[16][64];

    const int t   = threadIdx.x;
    const int lr  = t >> 2;
    const int lk4 = (t & 3) * 4;
    const int wr  = t >> 4;
    const int wc  = (t & 15) * 4;
    const int ty4 = (t >> 4) * 4;
    const int tx4 = (t & 15) * 4;

    const int mload = mtile * 64 + lr;
    const int hrow  = off + min(mload, cnt - 1);
    const float* arow = &g_hidden[(size_t)hrow * I_DIM];

    float acc[4][4] = {};

    for (int k0 = 0; k0 < I_DIM; k0 += 16) {
        float4 xa = *(const float4*)(arow + k0 + lk4);
        float4 bb = *(const float4*)(w2 + ((size_t)e * I_DIM + k0 + wr) * H_DIM + n0 + wc);
        __syncthreads();
        As[lk4 + 0][lr] = xa.x;
        As[lk4 + 1][lr] = xa.y;
        As[lk4 + 2][lr] = xa.z;
        As[lk4 + 3][lr] = xa.w;
        *(float4*)&Bs[wr][wc] = bb;
        __syncthreads();
#pragma unroll
        for (int kk = 0; kk < 16; kk++) {
            float a[4];
#pragma unroll
            for (int r = 0; r < 4; r++) a[r] = As[kk][ty4 + r];
            float4 v = *(const float4*)&Bs[kk][tx4];
            float bv[4] = {v.x, v.y, v.z, v.w};
#pragma unroll
            for (int r = 0; r < 4; r++)
#pragma unroll
                for (int c = 0; c < 4; c++)
                    acc[r][c] += a[r] * bv[c];
        }
    }

#pragma unroll
    for (int r = 0; r < 4; r++) {
        int m = mtile * 64 + ty4 + r;
        if (m < cnt) {
            int   tok = g_tok[e * T_TOK + m];
            float wgt = g_wt [e * T_TOK + m];
            float* orow = out + (size_t)tok * H_DIM + n0 + tx4;
#pragma unroll
            for (int c = 0; c < 4; c++)
                atomicAdd(orow + c, acc[r][c] * wgt);
        }
    }
}

// ---------------- launcher ----------------
extern "C" void kernel_launch(void* const* d_in, const int* in_sizes, int n_in,
                              void* d_out, int out_size) {
    const float* x   = (const float*)d_in[0];   // (B, S, H)
    const float* gw  = (const float*)d_in[1];   // (E, H)
    const float* w1  = (const float*)d_in[2];   // (E, H, I)
    const float* w3  = (const float*)d_in[3];   // (E, H, I)
    const float* w2  = (const float*)d_in[4];   // (E, I, H)
    float* out = (float*)d_out;                 // (B, S, H) fp32

    // 1. zero output (out_size = T*H floats; divisible by 4)
    int n4 = out_size / 4;
    zero_out_kernel<<<(n4 + 255) / 256, 256>>>(out, n4);

    // 2. zero per-expert counters
    zero_counts_kernel<<<1, 32>>>();

    // 3. router: 1 warp per token
    router_kernel<<<T_TOK / 4, 128>>>(x, gw);

    // 4. prefix offsets
    offsets_kernel<<<1, 32>>>();

    // 5. pass A: SwiGLU hidden per expert   grid: (I/64, ceil(T/64), E)
    {
        dim3 grid(I_DIM / 64, T_TOK / 64, E_NUM);
        moe_pass_a<<<grid, 256>>>(x, w1, w3);
    }

    // 6. pass B: down-proj + weighted scatter-add   grid: (H/64, ceil(T/64), E)
    {
        dim3 grid(H_DIM / 64, T_TOK / 64, E_NUM);
        moe_pass_b<<<grid, 256>>>(w2, out);
    }
}